// round 7
// baseline (speedup 1.0000x reference)
#include <cuda_runtime.h>
#include <cstddef>

// LoG = GaussianBlur(3,sigma=1) -> Laplacian(ksize=9) + 1, clip [0,255].
// Fused: composite 11x11 = A(x)B(y) + B(x)A(y), A = g3*S9, B = g3*D2_9.
// Reflect-101 pad of 5 on input == staged reflect pads (symmetric kernels).

#define Hn 512
#define Wn 512
#define ROWF 1536            // floats per image row (512*3)
#define TH 32
#define TWP 32
#define HALO 5
#define IN_H 42
#define IN_PITCH 132         // interleaved floats per smem row = 33 float4
#define IN_F4 33
#define HPP 68               // (A,B)-interleaved row pitch (float units)
#define HAB_PLANE 2860       // 42*68=2856 +4 pad; multiple of 4 (float4-safe)
#define NTHREADS 512

__device__ __forceinline__ int reflect101(int i, int n) {
    i = (i < 0) ? -i : i;
    return (i >= n) ? (2 * n - 2 - i) : i;
}

__global__ __launch_bounds__(NTHREADS, 4)
void log_fused_kernel(const float* __restrict__ x, float* __restrict__ out) {
    extern __shared__ float smem[];
    float* in_s  = smem;                           // [42][132] interleaved input
    float* hAB_s = smem + IN_H * IN_PITCH;         // 3 planes [42][HPP], (A,B) pairs

    const float cA[11] = {
        0.274068619061f,  2.644411714f, 11.562892048f, 30.192548953f,
        52.163039333f,   62.326078667f, 52.163039333f, 30.192548953f,
        11.562892048f,    2.644411714f,  0.274068619061f };
    const float cB[11] = {
        0.274068619061f,  1.548137238f,  3.177794143f,  1.807451048f,
       -3.451862762f,    -6.711176571f, -3.451862762f,  1.807451048f,
        3.177794143f,     1.548137238f,  0.274068619061f };

    const int tid = threadIdx.x;
    const int h0  = blockIdx.y * TH;
    const int p0  = blockIdx.x * TWP;
    const size_t plane = (size_t)blockIdx.z * (size_t)(Hn * ROWF);
    const float* xp = x + plane;

    // ====== Phase 1: gmem -> smem straight interleaved copy (reflect rows) ===
    // smem row r, col j holds input float F = 3*p0 - 16 + j (16B aligned base).
    if (p0 != 0 && p0 != (Wn - TWP)) {
        const float4* gbase = (const float4*)(xp + 3 * p0 - 16);
        float4* s4 = (float4*)in_s;
        #pragma unroll
        for (int k = 0; k < 3; k++) {
            const int idx = tid + k * NTHREADS;
            if (idx < IN_H * IN_F4) {
                const int r  = idx / IN_F4;
                const int c4 = idx - r * IN_F4;
                const int gh = reflect101(h0 - HALO + r, Hn);
                s4[idx] = gbase[gh * (ROWF / 4) + c4];
            }
        }
    } else {
        // border in W: scalar with per-float pixel reflection
        for (int v = tid; v < 4 * IN_PITCH; v += NTHREADS) {
            const int col = v % IN_PITCH;
            const int rg  = v / IN_PITCH;              // 0..3
            const int F   = 3 * p0 - 16 + col;
            const int P   = (F + 48) / 3 - 16;         // floor(F/3)
            const int ch  = F - 3 * P;
            const int sp  = reflect101(P, Wn);
            const int srcf = 3 * sp + ch;
            for (int r = rg; r < IN_H; r += 4) {
                const int gh = reflect101(h0 - HALO + r, Hn);
                in_s[r * IN_PITCH + col] = xp[(size_t)gh * ROWF + srcf];
            }
        }
    }
    __syncthreads();

    // ====== Phase 2: horizontal 11-tap, interleaved reads, all channels ======
    // Task = (4-pixel segment s, row r): 11 LDS.128 (44 floats, uses 1..42),
    // computes A,B for 4 pixels x 3 channels; channel demux is compile-time.
    if (tid < 336) {
        const int s = tid / IN_H;                     // 0..7
        const int r = tid - s * IN_H;
        const float4* src4 = (const float4*)(in_s + r * IN_PITCH) + 3 * s;

        float aA[3][4], aB[3][4];
        #pragma unroll
        for (int ch = 0; ch < 3; ch++)
            #pragma unroll
            for (int j = 0; j < 4; j++) { aA[ch][j] = 0.f; aB[ch][j] = 0.f; }

        #pragma unroll
        for (int k = 0; k < 11; k++) {
            float4 w = src4[k];
            float ws[4] = {w.x, w.y, w.z, w.w};
            #pragma unroll
            for (int u = 0; u < 4; u++) {
                const int i = 4 * k + u;              // local float index
                if (i >= 1 && i <= 42) {
                    const int m  = (i - 1) / 3;       // local pixel 0..13
                    const int ch = (i - 1) % 3;
                    const float v = ws[u];
                    #pragma unroll
                    for (int j = 0; j < 4; j++) {
                        const int t = m - j;
                        if (t >= 0 && t < 11) {
                            aA[ch][j] = fmaf(cA[t], v, aA[ch][j]);
                            aB[ch][j] = fmaf(cB[t], v, aB[ch][j]);
                        }
                    }
                }
            }
        }
        #pragma unroll
        for (int ch = 0; ch < 3; ch++) {
            float4* d = (float4*)(hAB_s + ch * HAB_PLANE + r * HPP + 8 * s);
            d[0] = make_float4(aA[ch][0], aB[ch][0], aA[ch][1], aB[ch][1]);
            d[1] = make_float4(aA[ch][2], aB[ch][2], aA[ch][3], aB[ch][3]);
        }
    }
    __syncthreads();

    // ====== Phase 3: vertical 11-tap combine, scalar FFMA, 8-row chunks =====
    // 96 output columns (32 px * 3 ch) * 4 chunks of 8 rows = 384 tasks.
    if (tid < 384) {
        const int col   = tid % 96;       // consecutive tid -> consecutive floats
        const int chunk = tid / 96;
        const int p = col / 3;
        const int c = col - p * 3;
        const int r0 = chunk * 8;
        const float2* s = (const float2*)(hAB_s + c * HAB_PLANE + r0 * HPP + 2 * p);

        float acc[8];
        #pragma unroll
        for (int j = 0; j < 8; j++) acc[j] = 1.0f;    // delta = 1

        #pragma unroll
        for (int i = 0; i < 18; i++) {
            const float2 v = s[i * (HPP / 2)];        // (A, B)
            #pragma unroll
            for (int j = 0; j < 8; j++) {
                const int t = i - j;
                if (t >= 0 && t < 11) {
                    acc[j] = fmaf(cB[t], v.x, acc[j]);
                    acc[j] = fmaf(cA[t], v.y, acc[j]);
                }
            }
        }
        float* op = out + plane + (size_t)(h0 + r0) * ROWF + p0 * 3 + col;
        #pragma unroll
        for (int j = 0; j < 8; j++) {
            op[j * ROWF] = fminf(fmaxf(acc[j], 0.0f), 255.0f);
        }
    }
}

extern "C" void kernel_launch(void* const* d_in, const int* in_sizes, int n_in,
                              void* d_out, int out_size) {
    const float* x = (const float*)d_in[0];
    float* out = (float*)d_out;
    const int N = in_sizes[0] / (Hn * Wn * 3);

    const int smem_bytes = (IN_H * IN_PITCH + 3 * HAB_PLANE) * (int)sizeof(float);
    cudaFuncSetAttribute(log_fused_kernel,
                         cudaFuncAttributeMaxDynamicSharedMemorySize, smem_bytes);

    dim3 grid(Wn / TWP, Hn / TH, N);   // (16, 16, N)
    log_fused_kernel<<<grid, NTHREADS, smem_bytes>>>(x, out);
}

// round 8
// speedup vs baseline: 1.3520x; 1.3520x over previous
#include <cuda_runtime.h>
#include <cstddef>

// LoG = GaussianBlur(3,sigma=1) -> Laplacian(ksize=9) + 1, clip [0,255].
// Fused: composite 11x11 = A(x)B(y) + B(x)A(y), A = g3*S9, B = g3*D2_9.
// Reflect-101 pad of 5 on input == staged reflect pads (symmetric kernels).

#define Hn 512
#define Wn 512
#define ROWF 1536            // floats per image row (512*3)
#define TH 32
#define TWP 32
#define HALO 5
#define IN_H 42
#define IN_WP 42
#define IN_PITCH 44          // 16B-aligned rows (deinterleaved channel planes)
#define IN_PLANE 1848        // 42*44
#define HPP 66               // (A,B) float2 row pitch = 33 (odd -> perfect STS banks)
#define HAB_PLANE 2774       // 42*66=2772 +2; /2 = 1387 == 11 mod 16 -> perfect LDS banks
#define NTHREADS 512

__device__ __forceinline__ int reflect101(int i, int n) {
    i = (i < 0) ? -i : i;
    return (i >= n) ? (2 * n - 2 - i) : i;
}

__global__ __launch_bounds__(NTHREADS, 4)
void log_fused_kernel(const float* __restrict__ x, float* __restrict__ out) {
    extern __shared__ float smem[];
    float* in_s  = smem;                       // 3 planes [IN_H][IN_PITCH]
    float* hAB_s = smem + 3 * IN_PLANE;        // 3 planes [IN_H][33 float2] (A,B)

    const float cA[11] = {
        0.274068619061f,  2.644411714f, 11.562892048f, 30.192548953f,
        52.163039333f,   62.326078667f, 52.163039333f, 30.192548953f,
        11.562892048f,    2.644411714f,  0.274068619061f };
    const float cB[11] = {
        0.274068619061f,  1.548137238f,  3.177794143f,  1.807451048f,
       -3.451862762f,    -6.711176571f, -3.451862762f,  1.807451048f,
        3.177794143f,     1.548137238f,  0.274068619061f };

    const int tid = threadIdx.x;
    const int h0  = blockIdx.y * TH;
    const int p0  = blockIdx.x * TWP;
    const size_t plane = (size_t)blockIdx.z * (size_t)(Hn * ROWF);
    const float* xp = x + plane;

    // ================= Phase 1: gmem -> smem (deinterleave, reflect-101) ======
    if (p0 != 0 && p0 != (Wn - TWP)) {
        // interior-W fast path: float4 loads, no column reflect math
        const int fidx0 = (p0 - HALO) * 3 - 1;       // 16B-aligned start
        const int col4  = tid & 31;
        int r = tid >> 5;                            // 0..15

        int qq[4], cc[4];
        bool val[4];
        #pragma unroll
        for (int l = 0; l < 4; l++) {
            int off = 4 * col4 + l - 1;
            val[l] = (off >= 0) && (off < IN_WP * 3);
            int o = val[l] ? off : 0;
            qq[l] = o / 3;
            cc[l] = o - 3 * qq[l];
        }
        const float4* gp = (const float4*)(xp + fidx0 + 4 * col4);

        #pragma unroll
        for (int k = 0; k < 3; k++) {
            if (r < IN_H) {
                const int gh = reflect101(h0 - HALO + r, Hn);
                float4 v = gp[gh * (ROWF / 4)];
                float vv[4] = {v.x, v.y, v.z, v.w};
                const int rb = r * IN_PITCH;
                #pragma unroll
                for (int l = 0; l < 4; l++) {
                    if (val[l]) in_s[cc[l] * IN_PLANE + rb + qq[l]] = vv[l];
                }
            }
            r += 16;
        }
    } else {
        // border-W scalar path (reflect both dims)
        const int f  = tid & 127;
        const int rg = tid >> 7;                     // 0..3
        if (f < IN_WP * 3) {
            const int q = f / 3;
            const int c = f - q * 3;
            const int wp = reflect101(p0 - HALO + q, Wn);
            const int src_col = wp * 3 + c;
            float* dst = in_s + c * IN_PLANE + q;
            #pragma unroll 4
            for (int r = rg; r < IN_H; r += 4) {
                const int gh = reflect101(h0 - HALO + r, Hn);
                dst[r * IN_PITCH] = xp[(size_t)gh * ROWF + src_col];
            }
        }
    }
    __syncthreads();

    // ========== Phase 2: horizontal 11-tap (A and B), vectorized reads =======
    // 3 ch * 42 rows * 4 eight-output segments = 504 tasks, one per thread.
    if (tid < 504) {
        const int c   = tid / (IN_H * 4);
        const int rem = tid - c * (IN_H * 4);
        const int r   = rem >> 2;
        const int p   = (rem & 3) << 3;
        const float* src = in_s + c * IN_PLANE + r * IN_PITCH + p;

        float aA[8], aB[8];
        #pragma unroll
        for (int j = 0; j < 8; j++) { aA[j] = 0.f; aB[j] = 0.f; }

        // 18-float window: 4x LDS.128 + 1x LDS.64, streamed into accumulators
        #pragma unroll
        for (int ib = 0; ib < 4; ib++) {
            float4 v4 = *(const float4*)(src + 4 * ib);
            float vs[4] = {v4.x, v4.y, v4.z, v4.w};
            #pragma unroll
            for (int s = 0; s < 4; s++) {
                const int i = 4 * ib + s;
                const float v = vs[s];
                #pragma unroll
                for (int j = 0; j < 8; j++) {
                    const int t = i - j;
                    if (t >= 0 && t < 11) {
                        aA[j] = fmaf(cA[t], v, aA[j]);
                        aB[j] = fmaf(cB[t], v, aB[j]);
                    }
                }
            }
        }
        {
            float2 v2 = *(const float2*)(src + 16);
            float vs[2] = {v2.x, v2.y};
            #pragma unroll
            for (int s = 0; s < 2; s++) {
                const int i = 16 + s;
                const float v = vs[s];
                #pragma unroll
                for (int j = 0; j < 8; j++) {
                    const int t = i - j;
                    if (t >= 0 && t < 11) {
                        aA[j] = fmaf(cA[t], v, aA[j]);
                        aB[j] = fmaf(cB[t], v, aB[j]);
                    }
                }
            }
        }

        // (A,B) pairs -> 8x STS.64 (perfect 2-way banks: odd float2 pitch)
        float2* d = (float2*)(hAB_s + c * HAB_PLANE + r * HPP) + p;
        #pragma unroll
        for (int j = 0; j < 8; j++) d[j] = make_float2(aA[j], aB[j]);
    }
    __syncthreads();

    // ========== Phase 3: vertical 11-tap combine, 16-row chunks ==============
    // 96 output columns (32 px * 3 ch) * 2 chunks of 16 rows = 192 tasks.
    // 26 LDS.64 per 16 outputs; plane/2 == 11 mod 16 -> exact 2-wf bank cover.
    if (tid < 192) {
        const int col   = tid % 96;       // consecutive tid -> consecutive floats
        const int chunk = tid / 96;
        const int p = col / 3;
        const int c = col - p * 3;
        const int r0 = chunk * 16;
        const float2* s = (const float2*)(hAB_s + c * HAB_PLANE) + r0 * (HPP / 2) + p;

        float acc[16];
        #pragma unroll
        for (int j = 0; j < 16; j++) acc[j] = 1.0f;   // delta = 1

        #pragma unroll
        for (int i = 0; i < 26; i++) {
            const float2 v = s[i * (HPP / 2)];        // (A, B)
            #pragma unroll
            for (int j = 0; j < 16; j++) {
                const int t = i - j;
                if (t >= 0 && t < 11) {
                    acc[j] = fmaf(cB[t], v.x, acc[j]);
                    acc[j] = fmaf(cA[t], v.y, acc[j]);
                }
            }
        }
        float* op = out + plane + (size_t)(h0 + r0) * ROWF + p0 * 3 + col;
        #pragma unroll
        for (int j = 0; j < 16; j++) {
            op[j * ROWF] = fminf(fmaxf(acc[j], 0.0f), 255.0f);
        }
    }
}

extern "C" void kernel_launch(void* const* d_in, const int* in_sizes, int n_in,
                              void* d_out, int out_size) {
    const float* x = (const float*)d_in[0];
    float* out = (float*)d_out;
    const int N = in_sizes[0] / (Hn * Wn * 3);

    const int smem_bytes = (3 * IN_PLANE + 3 * HAB_PLANE) * (int)sizeof(float);
    cudaFuncSetAttribute(log_fused_kernel,
                         cudaFuncAttributeMaxDynamicSharedMemorySize, smem_bytes);

    dim3 grid(Wn / TWP, Hn / TH, N);   // (16, 16, N)
    log_fused_kernel<<<grid, NTHREADS, smem_bytes>>>(x, out);
}